// round 5
// baseline (speedup 1.0000x reference)
#include <cuda_runtime.h>
#include <cuda_bf16.h>
#include <cstdint>
#include <cstddef>

// ============================================================================
// Problem: B=8, M=2048 -> NTOK=16384 tokens, feature dim 1024, H=16, Kd=Vd=64.
// split fp32->bf16(hi,lo); 3-pass hi/lo HMMA GEMMs; fp32 attention core; out GEMM.
// Target is plain sm_100 (no tcgen05) -> mma.sync + ldmatrix + cp.async.
// R5: GEMM loads {Ahi,Alo,Bhi,Blo} ONCE per k-tile and runs all 3 passes from
// that smem residency (-33% L2 traffic, 3x fewer barriers). Splits fused.
// ============================================================================
constexpr int NTOK = 16384;
constexpr int FDIM = 1024;
constexpr int NELEM_X = NTOK * FDIM;
constexpr int NELEM_W = FDIM * FDIM;

__device__ __nv_bfloat16 g_x1hi[NELEM_X];
__device__ __nv_bfloat16 g_x1lo[NELEM_X];
__device__ __nv_bfloat16 g_x2hi[NELEM_X];
__device__ __nv_bfloat16 g_x2lo[NELEM_X];
__device__ __nv_bfloat16 g_wqhi[NELEM_W];
__device__ __nv_bfloat16 g_wqlo[NELEM_W];
__device__ __nv_bfloat16 g_wkhi[NELEM_W];
__device__ __nv_bfloat16 g_wklo[NELEM_W];
__device__ __nv_bfloat16 g_wvhi[NELEM_W];
__device__ __nv_bfloat16 g_wvlo[NELEM_W];
__device__ __nv_bfloat16 g_wohi[NELEM_W];
__device__ __nv_bfloat16 g_wolo[NELEM_W];
__device__ float g_q1[NELEM_X];
__device__ float g_k2[NELEM_X];
__device__ float g_v2[NELEM_X];
__device__ __nv_bfloat16 g_mhi[NELEM_X];
__device__ __nv_bfloat16 g_mlo[NELEM_X];

#define DINL __device__ __forceinline__

DINL uint32_t smem_u32(const void* p) {
    uint32_t a;
    asm("{ .reg .u64 t; cvta.to.shared.u64 t, %1; cvt.u32.u64 %0, t; }"
        : "=r"(a) : "l"(p));
    return a;
}

#define SW128(o) ((o) ^ (((o) >> 3) & 0x70))

#define CP_ASYNC16(smem_addr, gptr) \
    asm volatile("cp.async.cg.shared.global [%0], [%1], 16;" \
                 :: "r"(smem_addr), "l"(gptr))
#define CP_COMMIT() asm volatile("cp.async.commit_group;")
#define CP_WAIT(n)  asm volatile("cp.async.wait_group %0;" :: "n"(n))

#define LDSM_X4(r0, r1, r2, r3, addr) \
    asm volatile("ldmatrix.sync.aligned.m8n8.x4.shared.b16 {%0,%1,%2,%3}, [%4];" \
                 : "=r"(r0), "=r"(r1), "=r"(r2), "=r"(r3) : "r"(addr))

DINL void mma16816(float* c, const uint32_t* a, const uint32_t* b) {
    asm volatile(
        "mma.sync.aligned.m16n8k16.row.col.f32.bf16.bf16.f32 "
        "{%0,%1,%2,%3}, {%4,%5,%6,%7}, {%8,%9}, {%0,%1,%2,%3};"
        : "+f"(c[0]), "+f"(c[1]), "+f"(c[2]), "+f"(c[3])
        : "r"(a[0]), "r"(a[1]), "r"(a[2]), "r"(a[3]), "r"(b[0]), "r"(b[1]));
}

// ============================================================================
// Fused fp32 -> (bf16 hi, bf16 lo) split for all 6 tensors in ONE launch.
// ============================================================================
struct SplitArgs {
    const float* in[6];
    __nv_bfloat16* hi[6];
    __nv_bfloat16* lo[6];
    int n4[6];
};

__global__ void __launch_bounds__(256) split_all_kernel(SplitArgs args)
{
    const int a = blockIdx.y;
    const int i = blockIdx.x * 256 + threadIdx.x;
    if (i >= args.n4[a]) return;
    float4 v = reinterpret_cast<const float4*>(args.in[a])[i];

    __nv_bfloat16 h0 = __float2bfloat16(v.x);
    __nv_bfloat16 h1 = __float2bfloat16(v.y);
    __nv_bfloat16 h2 = __float2bfloat16(v.z);
    __nv_bfloat16 h3 = __float2bfloat16(v.w);
    __nv_bfloat16 l0 = __float2bfloat16(v.x - __bfloat162float(h0));
    __nv_bfloat16 l1 = __float2bfloat16(v.y - __bfloat162float(h1));
    __nv_bfloat16 l2 = __float2bfloat16(v.z - __bfloat162float(h2));
    __nv_bfloat16 l3 = __float2bfloat16(v.w - __bfloat162float(h3));

    __nv_bfloat162 hp0; hp0.x = h0; hp0.y = h1;
    __nv_bfloat162 hp1; hp1.x = h2; hp1.y = h3;
    __nv_bfloat162 lp0; lp0.x = l0; lp0.y = l1;
    __nv_bfloat162 lp1; lp1.x = l2; lp1.y = l3;
    uint2 uh, ul;
    uh.x = *reinterpret_cast<uint32_t*>(&hp0);
    uh.y = *reinterpret_cast<uint32_t*>(&hp1);
    ul.x = *reinterpret_cast<uint32_t*>(&lp0);
    ul.y = *reinterpret_cast<uint32_t*>(&lp1);
    reinterpret_cast<uint2*>(args.hi[a])[i] = uh;
    reinterpret_cast<uint2*>(args.lo[a])[i] = ul;
}

// ============================================================================
// Split-bf16 GEMM via mma.sync: C[m,n] = sum_k A[m,k]*B[n,k] (+bias)
// Per k-tile, loads {Ahi, Alo, Bhi, Blo} (4 x 16KB) once and runs all 3 hi/lo
// passes (Ahi*Bhi + Alo*Bhi + Ahi*Blo) from that residency.
// CTA 128x128, BK=64, 3-stage x 64KB cp.async pipeline (192 KB smem),
// register-double-buffered ldmatrix fragments over 12 (pass,kstep) slots.
// ============================================================================
constexpr int BM = 128, BN = 128, BK = 64;
constexpr int STAGES = 3;
constexpr int NKT = FDIM / BK;                // 16
constexpr int TILEB = 128 * 128;              // 16 KB
constexpr int STAGE_BYTES = 4 * TILEB;        // AH AL BH BL = 64 KB
constexpr int GEMM_SMEM = STAGES * STAGE_BYTES;   // 192 KB

__global__ void __launch_bounds__(256) gemm_hmma_kernel(
    const __nv_bfloat16* __restrict__ Ahi, const __nv_bfloat16* __restrict__ Alo,
    const __nv_bfloat16* __restrict__ Bhi, const __nv_bfloat16* __restrict__ Blo,
    float* __restrict__ C, const float* __restrict__ bias)
{
    extern __shared__ __align__(1024) char smem[];
    const uint32_t sbase = smem_u32(smem);
    const int tid = threadIdx.x;
    const int wid = tid >> 5;
    const int lid = tid & 31;
    const int wm = wid & 1;
    const int wn = wid >> 1;
    const int m0 = blockIdx.y * BM;
    const int n0 = blockIdx.x * BN;

    float acc[4][4][4];
    #pragma unroll
    for (int i = 0; i < 4; ++i)
        #pragma unroll
        for (int j = 0; j < 4; ++j)
            #pragma unroll
            for (int r = 0; r < 4; ++r) acc[i][j][r] = 0.f;

    // per-lane ldmatrix address components
    const int arow_base = wm * 64 + ((lid >> 3) & 1) * 8 + (lid & 7);
    const int akoff     = (lid >> 4) * 16;
    const int brow_base = wn * 32 + ((lid >> 4) & 1) * 8 + (lid & 7);
    const int bkoff     = ((lid >> 3) & 1) * 16;

    // Load one k-tile's 4 operand tiles into stage `buf`.
    auto load_stage = [&](int buf, int kt) {
        const int k0 = kt * BK;
        const uint32_t st = sbase + buf * STAGE_BYTES;
        #pragma unroll
        for (int i = 0; i < 4; ++i) {
            int chunk = tid + i * 256;           // 0..1023
            int r = chunk >> 3;                   // row 0..127
            int c = chunk & 7;                    // 16B chunk
            uint32_t sw = SW128((uint32_t)(r * 128 + c * 16));
            const size_t aoff = (size_t)(m0 + r) * FDIM + k0 + c * 8;
            const size_t boff = (size_t)(n0 + r) * FDIM + k0 + c * 8;
            CP_ASYNC16(st + sw,             Ahi + aoff);
            CP_ASYNC16(st + TILEB + sw,     Alo + aoff);
            CP_ASYNC16(st + 2 * TILEB + sw, Bhi + boff);
            CP_ASYNC16(st + 3 * TILEB + sw, Blo + boff);
        }
    };

    // Fragment load for slot idx in [0,12): pass p = idx>>2, kstep ks = idx&3.
    // A source: pass1 -> Alo else Ahi.  B source: pass2 -> Blo else Bhi.
    auto load_frags = [&](uint32_t st, int idx,
                          uint32_t (*af)[4], uint32_t (*bf_)[2]) {
        const int p = idx >> 2;
        const int ks = idx & 3;
        const uint32_t sa = st + (p == 1 ? TILEB : 0u);
        const uint32_t sb = st + 2 * TILEB + (p == 2 ? TILEB : 0u);
        #pragma unroll
        for (int mt = 0; mt < 4; ++mt) {
            uint32_t ad = sa + SW128((uint32_t)((arow_base + mt * 16) * 128 +
                                                ks * 32 + akoff));
            LDSM_X4(af[mt][0], af[mt][1], af[mt][2], af[mt][3], ad);
        }
        #pragma unroll
        for (int bt = 0; bt < 2; ++bt) {
            uint32_t bd = sb + SW128((uint32_t)((brow_base + bt * 16) * 128 +
                                                ks * 32 + bkoff));
            LDSM_X4(bf_[2 * bt][0], bf_[2 * bt][1],
                    bf_[2 * bt + 1][0], bf_[2 * bt + 1][1], bd);
        }
    };

    // prologue
    load_stage(0, 0); CP_COMMIT();
    load_stage(1, 1); CP_COMMIT();

    uint32_t af[2][4][4];
    uint32_t bf_[2][4][2];

    for (int kt = 0; kt < NKT; ++kt) {
        CP_WAIT(STAGES - 2);
        __syncthreads();

        int nxt = kt + STAGES - 1;
        if (nxt < NKT) load_stage(nxt % STAGES, nxt);
        CP_COMMIT();

        const uint32_t st = sbase + (kt % STAGES) * STAGE_BYTES;

        load_frags(st, 0, af[0], bf_[0]);
        #pragma unroll
        for (int idx = 0; idx < 12; ++idx) {
            const int cur = idx & 1;
            if (idx < 11) load_frags(st, idx + 1, af[cur ^ 1], bf_[cur ^ 1]);
            #pragma unroll
            for (int mt = 0; mt < 4; ++mt)
                #pragma unroll
                for (int nt = 0; nt < 4; ++nt)
                    mma16816(acc[mt][nt], af[cur][mt], bf_[cur][nt]);
        }
    }

    // epilogue
    const int g = lid >> 2;
    const int t = lid & 3;
    #pragma unroll
    for (int mt = 0; mt < 4; ++mt) {
        #pragma unroll
        for (int nt = 0; nt < 4; ++nt) {
            int row0 = m0 + wm * 64 + mt * 16 + g;
            int col  = n0 + wn * 32 + nt * 8 + 2 * t;
            float bx = 0.f, by = 0.f;
            if (bias != nullptr) {
                float2 bv = *reinterpret_cast<const float2*>(bias + col);
                bx = bv.x; by = bv.y;
            }
            float2 v0 = make_float2(acc[mt][nt][0] + bx, acc[mt][nt][1] + by);
            float2 v1 = make_float2(acc[mt][nt][2] + bx, acc[mt][nt][3] + by);
            *reinterpret_cast<float2*>(C + (size_t)row0 * FDIM + col) = v0;
            *reinterpret_cast<float2*>(C + (size_t)(row0 + 8) * FDIM + col) = v1;
        }
    }
}

// ============================================================================
// Per-token attention core (fp32), float4-vectorized smem traffic.
// ============================================================================
__global__ void __launch_bounds__(128) middle_kernel(
    const float* __restrict__ q, const float* __restrict__ k,
    const float* __restrict__ v,
    __nv_bfloat16* __restrict__ mhi, __nv_bfloat16* __restrict__ mlo)
{
    __shared__ float sq[1024];
    __shared__ float sk[1024];
    __shared__ float sv[1024];
    __shared__ float sat[64 * 65];

    const int t = blockIdx.x;
    const int tid = threadIdx.x;
    const size_t base = (size_t)t * 1024;

    {
        const float4* qs = reinterpret_cast<const float4*>(q + base);
        const float4* ks = reinterpret_cast<const float4*>(k + base);
        const float4* vs = reinterpret_cast<const float4*>(v + base);
        float4* dq = reinterpret_cast<float4*>(sq);
        float4* dk = reinterpret_cast<float4*>(sk);
        float4* dv = reinterpret_cast<float4*>(sv);
        dq[tid] = qs[tid]; dq[tid + 128] = qs[tid + 128];
        dk[tid] = ks[tid]; dk[tid + 128] = ks[tid + 128];
        dv[tid] = vs[tid]; dv[tid + 128] = vs[tid + 128];
    }
    __syncthreads();

    const int d = tid & 63;
    const int cg = tid >> 6;

    float qreg[16];
    #pragma unroll
    for (int h = 0; h < 16; ++h) qreg[h] = sq[h * 64 + d];

    #pragma unroll
    for (int cb = 0; cb < 8; ++cb) {
        const int c0 = cg * 32 + cb * 4;
        float4 a4 = make_float4(0.f, 0.f, 0.f, 0.f);
        #pragma unroll
        for (int h = 0; h < 16; ++h) {
            float4 k4 = *reinterpret_cast<const float4*>(&sk[h * 64 + c0]);
            float qh = qreg[h];
            a4.x += k4.x * qh; a4.y += k4.y * qh;
            a4.z += k4.z * qh; a4.w += k4.w * qh;
        }
        sat[(c0 + 0) * 65 + d] = a4.x * 0.125f;
        sat[(c0 + 1) * 65 + d] = a4.y * 0.125f;
        sat[(c0 + 2) * 65 + d] = a4.z * 0.125f;
        sat[(c0 + 3) * 65 + d] = a4.w * 0.125f;
    }
    __syncthreads();

    if (tid < 64) {
        const int c = tid;
        float m = -1e30f;
        for (int dd = 0; dd < 64; ++dd) m = fmaxf(m, sat[c * 65 + dd]);
        float s = 0.f;
        for (int dd = 0; dd < 64; ++dd) {
            float e = __expf(sat[c * 65 + dd] - m);
            sat[c * 65 + dd] = e;
            s += e;
        }
        float inv = 1.f / s;
        for (int dd = 0; dd < 64; ++dd) sat[c * 65 + dd] *= inv;
    }
    __syncthreads();

    float a8[8];
    #pragma unroll
    for (int j = 0; j < 8; ++j) a8[j] = 0.f;
    #pragma unroll 4
    for (int vb = 0; vb < 16; ++vb) {
        const int v0 = vb * 4;
        float s0 = sat[(v0 + 0) * 65 + d];
        float s1 = sat[(v0 + 1) * 65 + d];
        float s2 = sat[(v0 + 2) * 65 + d];
        float s3 = sat[(v0 + 3) * 65 + d];
        #pragma unroll
        for (int j = 0; j < 8; ++j) {
            float4 v4 = *reinterpret_cast<const float4*>(&sv[(cg * 8 + j) * 64 + v0]);
            a8[j] += v4.x * s0 + v4.y * s1 + v4.z * s2 + v4.w * s3;
        }
    }
    #pragma unroll
    for (int j = 0; j < 8; ++j) {
        float x = a8[j];
        __nv_bfloat16 h = __float2bfloat16(x);
        __nv_bfloat16 l = __float2bfloat16(x - __bfloat162float(h));
        size_t idx = base + (size_t)(cg * 8 + j) * 64 + d;
        mhi[idx] = h;
        mlo[idx] = l;
    }
}

// ============================================================================
// kernel_launch: [split_all, gemmQ, gemmK, gemmV, middle, gemmO]
// ============================================================================
extern "C" void kernel_launch(void* const* d_in, const int* in_sizes, int n_in,
                              void* d_out, int out_size)
{
    const float* x1 = (const float*)d_in[0];
    const float* x2 = (const float*)d_in[1];
    const float* Wq = (const float*)d_in[2];
    const float* Wk = (const float*)d_in[3];
    const float* Wv = (const float*)d_in[4];
    const float* Wo = (const float*)d_in[5];
    const float* bo = (const float*)d_in[6];
    float* out = (float*)d_out;

    void *px1h, *px1l, *px2h, *px2l;
    void *pwqh, *pwql, *pwkh, *pwkl, *pwvh, *pwvl, *pwoh, *pwol;
    void *pq1, *pk2, *pv2, *pmh, *pml;
    cudaGetSymbolAddress(&px1h, g_x1hi); cudaGetSymbolAddress(&px1l, g_x1lo);
    cudaGetSymbolAddress(&px2h, g_x2hi); cudaGetSymbolAddress(&px2l, g_x2lo);
    cudaGetSymbolAddress(&pwqh, g_wqhi); cudaGetSymbolAddress(&pwql, g_wqlo);
    cudaGetSymbolAddress(&pwkh, g_wkhi); cudaGetSymbolAddress(&pwkl, g_wklo);
    cudaGetSymbolAddress(&pwvh, g_wvhi); cudaGetSymbolAddress(&pwvl, g_wvlo);
    cudaGetSymbolAddress(&pwoh, g_wohi); cudaGetSymbolAddress(&pwol, g_wolo);
    cudaGetSymbolAddress(&pq1, g_q1);   cudaGetSymbolAddress(&pk2, g_k2);
    cudaGetSymbolAddress(&pv2, g_v2);
    cudaGetSymbolAddress(&pmh, g_mhi);  cudaGetSymbolAddress(&pml, g_mlo);

    cudaFuncSetAttribute(gemm_hmma_kernel,
                         cudaFuncAttributeMaxDynamicSharedMemorySize, GEMM_SMEM);

    const int n4x = NELEM_X / 4;   // 4,194,304
    const int n4w = NELEM_W / 4;   // 262,144

    SplitArgs sa;
    sa.in[0] = x1; sa.hi[0] = (__nv_bfloat16*)px1h; sa.lo[0] = (__nv_bfloat16*)px1l; sa.n4[0] = n4x;
    sa.in[1] = x2; sa.hi[1] = (__nv_bfloat16*)px2h; sa.lo[1] = (__nv_bfloat16*)px2l; sa.n4[1] = n4x;
    sa.in[2] = Wq; sa.hi[2] = (__nv_bfloat16*)pwqh; sa.lo[2] = (__nv_bfloat16*)pwql; sa.n4[2] = n4w;
    sa.in[3] = Wk; sa.hi[3] = (__nv_bfloat16*)pwkh; sa.lo[3] = (__nv_bfloat16*)pwkl; sa.n4[3] = n4w;
    sa.in[4] = Wv; sa.hi[4] = (__nv_bfloat16*)pwvh; sa.lo[4] = (__nv_bfloat16*)pwvl; sa.n4[4] = n4w;
    sa.in[5] = Wo; sa.hi[5] = (__nv_bfloat16*)pwoh; sa.lo[5] = (__nv_bfloat16*)pwol; sa.n4[5] = n4w;

    dim3 sg(n4x / 256, 6);
    split_all_kernel<<<sg, 256>>>(sa);

    dim3 gg(FDIM / BN, NTOK / BM);   // (8, 128)
    gemm_hmma_kernel<<<gg, 256, GEMM_SMEM>>>(
        (const __nv_bfloat16*)px1h, (const __nv_bfloat16*)px1l,
        (const __nv_bfloat16*)pwqh, (const __nv_bfloat16*)pwql,
        (float*)pq1, nullptr);
    gemm_hmma_kernel<<<gg, 256, GEMM_SMEM>>>(
        (const __nv_bfloat16*)px2h, (const __nv_bfloat16*)px2l,
        (const __nv_bfloat16*)pwkh, (const __nv_bfloat16*)pwkl,
        (float*)pk2, nullptr);
    gemm_hmma_kernel<<<gg, 256, GEMM_SMEM>>>(
        (const __nv_bfloat16*)px2h, (const __nv_bfloat16*)px2l,
        (const __nv_bfloat16*)pwvh, (const __nv_bfloat16*)pwvl,
        (float*)pv2, nullptr);

    middle_kernel<<<NTOK, 128>>>(
        (const float*)pq1, (const float*)pk2, (const float*)pv2,
        (__nv_bfloat16*)pmh, (__nv_bfloat16*)pml);

    gemm_hmma_kernel<<<gg, 256, GEMM_SMEM>>>(
        (const __nv_bfloat16*)pmh, (const __nv_bfloat16*)pml,
        (const __nv_bfloat16*)pwoh, (const __nv_bfloat16*)pwol,
        out, bo);
}

// round 6
// speedup vs baseline: 1.3226x; 1.3226x over previous
#include <cuda_runtime.h>
#include <cuda_fp16.h>
#include <cstdint>
#include <cstddef>

// ============================================================================
// Problem: B=8, M=2048 -> NTOK=16384 tokens, feature dim 1024, H=16, Kd=Vd=64.
// R6: fp16 2-pass GEMMs (A split hi/lo fp16, B single fp16):
//   C = Ahi*B + Alo*B ; error ~ A*(B - fp16(B)) ~ 1e-4 rel  (threshold 1e-3)
// -33% MMA work vs bf16 3-pass. GEMM: 512 threads (4 warps/SMSP), warp 32x32,
// 3-stage x 48KB cp.async pipeline. fp32 attention core unchanged.
// ============================================================================
constexpr int NTOK = 16384;
constexpr int FDIM = 1024;
constexpr int NELEM_X = NTOK * FDIM;
constexpr int NELEM_W = FDIM * FDIM;

__device__ __half g_x1hi[NELEM_X];
__device__ __half g_x1lo[NELEM_X];
__device__ __half g_x2hi[NELEM_X];
__device__ __half g_x2lo[NELEM_X];
__device__ __half g_wqf[NELEM_W];
__device__ __half g_wkf[NELEM_W];
__device__ __half g_wvf[NELEM_W];
__device__ __half g_wof[NELEM_W];
__device__ float g_q1[NELEM_X];
__device__ float g_k2[NELEM_X];
__device__ float g_v2[NELEM_X];
__device__ __half g_mhi[NELEM_X];
__device__ __half g_mlo[NELEM_X];

#define DINL __device__ __forceinline__

DINL uint32_t smem_u32(const void* p) {
    uint32_t a;
    asm("{ .reg .u64 t; cvta.to.shared.u64 t, %1; cvt.u32.u64 %0, t; }"
        : "=r"(a) : "l"(p));
    return a;
}

#define SW128(o) ((o) ^ (((o) >> 3) & 0x70))

#define CP_ASYNC16(smem_addr, gptr) \
    asm volatile("cp.async.cg.shared.global [%0], [%1], 16;" \
                 :: "r"(smem_addr), "l"(gptr))
#define CP_COMMIT() asm volatile("cp.async.commit_group;")
#define CP_WAIT(n)  asm volatile("cp.async.wait_group %0;" :: "n"(n))

#define LDSM_X4(r0, r1, r2, r3, addr) \
    asm volatile("ldmatrix.sync.aligned.m8n8.x4.shared.b16 {%0,%1,%2,%3}, [%4];" \
                 : "=r"(r0), "=r"(r1), "=r"(r2), "=r"(r3) : "r"(addr))

DINL void mma16816(float* c, const uint32_t* a, const uint32_t* b) {
    asm volatile(
        "mma.sync.aligned.m16n8k16.row.col.f32.f16.f16.f32 "
        "{%0,%1,%2,%3}, {%4,%5,%6,%7}, {%8,%9}, {%0,%1,%2,%3};"
        : "+f"(c[0]), "+f"(c[1]), "+f"(c[2]), "+f"(c[3])
        : "r"(a[0]), "r"(a[1]), "r"(a[2]), "r"(a[3]), "r"(b[0]), "r"(b[1]));
}

// ============================================================================
// Fused preprocessing, one launch: tensors with lo!=null get fp32->fp16 hi/lo
// split; tensors with lo==null get single fp16 convert.
// ============================================================================
struct SplitArgs {
    const float* in[6];
    __half* hi[6];
    __half* lo[6];   // nullptr => single-convert
    int n4[6];
};

__global__ void __launch_bounds__(256) split_all_kernel(SplitArgs args)
{
    const int a = blockIdx.y;
    const int i = blockIdx.x * 256 + threadIdx.x;
    if (i >= args.n4[a]) return;
    float4 v = reinterpret_cast<const float4*>(args.in[a])[i];

    __half h0 = __float2half(v.x);
    __half h1 = __float2half(v.y);
    __half h2 = __float2half(v.z);
    __half h3 = __float2half(v.w);
    __half2 hp0; hp0.x = h0; hp0.y = h1;
    __half2 hp1; hp1.x = h2; hp1.y = h3;
    uint2 uh;
    uh.x = *reinterpret_cast<uint32_t*>(&hp0);
    uh.y = *reinterpret_cast<uint32_t*>(&hp1);
    reinterpret_cast<uint2*>(args.hi[a])[i] = uh;

    if (args.lo[a] != nullptr) {
        __half l0 = __float2half(v.x - __half2float(h0));
        __half l1 = __float2half(v.y - __half2float(h1));
        __half l2 = __float2half(v.z - __half2float(h2));
        __half l3 = __float2half(v.w - __half2float(h3));
        __half2 lp0; lp0.x = l0; lp0.y = l1;
        __half2 lp1; lp1.x = l2; lp1.y = l3;
        uint2 ul;
        ul.x = *reinterpret_cast<uint32_t*>(&lp0);
        ul.y = *reinterpret_cast<uint32_t*>(&lp1);
        reinterpret_cast<uint2*>(args.lo[a])[i] = ul;
    }
}

// ============================================================================
// fp16 2-pass GEMM: C[m,n] = sum_k (Ahi+Alo)[m,k] * B[n,k] (+bias)
// CTA 128x128, 512 threads (16 warps, 4x4), warp tile 32x32, BK=64.
// Stage = {Ahi, Alo, B} = 48KB; 3 stages = 144KB. Per k-tile: 2 passes x
// 4 ksteps = 8 slots x 8 MMAs/warp, register double-buffered fragments.
// ============================================================================
constexpr int BM = 128, BN = 128, BK = 64;
constexpr int STAGES = 3;
constexpr int NKT = FDIM / BK;                // 16
constexpr int TILEB = 128 * 128;              // 16 KB
constexpr int STAGE_BYTES = 3 * TILEB;        // 48 KB
constexpr int GEMM_SMEM = STAGES * STAGE_BYTES;   // 144 KB

__global__ void __launch_bounds__(512) gemm_hmma_kernel(
    const __half* __restrict__ Ahi, const __half* __restrict__ Alo,
    const __half* __restrict__ Bf,
    float* __restrict__ C, const float* __restrict__ bias)
{
    extern __shared__ __align__(1024) char smem[];
    const uint32_t sbase = smem_u32(smem);
    const int tid = threadIdx.x;
    const int wid = tid >> 5;
    const int lid = tid & 31;
    const int wm = wid & 3;          // m group: rows wm*32 .. wm*32+31
    const int wn = wid >> 2;         // n group: cols wn*32 .. wn*32+31
    const int m0 = blockIdx.y * BM;
    const int n0 = blockIdx.x * BN;

    float acc[2][4][4];
    #pragma unroll
    for (int i = 0; i < 2; ++i)
        #pragma unroll
        for (int j = 0; j < 4; ++j)
            #pragma unroll
            for (int r = 0; r < 4; ++r) acc[i][j][r] = 0.f;

    const int arow_base = wm * 32 + ((lid >> 3) & 1) * 8 + (lid & 7);
    const int akoff     = (lid >> 4) * 16;
    const int brow_base = wn * 32 + ((lid >> 4) & 1) * 8 + (lid & 7);
    const int bkoff     = ((lid >> 3) & 1) * 16;

    // Load one k-tile's 3 operand tiles into stage `buf` (512 threads,
    // 2 chunks/thread/tile).
    auto load_stage = [&](int buf, int kt) {
        const int k0 = kt * BK;
        const uint32_t st = sbase + buf * STAGE_BYTES;
        #pragma unroll
        for (int i = 0; i < 2; ++i) {
            int chunk = tid + i * 512;            // 0..1023
            int r = chunk >> 3;                    // row 0..127
            int c = chunk & 7;                     // 16B chunk
            uint32_t sw = SW128((uint32_t)(r * 128 + c * 16));
            const size_t aoff = (size_t)(m0 + r) * FDIM + k0 + c * 8;
            const size_t boff = (size_t)(n0 + r) * FDIM + k0 + c * 8;
            CP_ASYNC16(st + sw,             Ahi + aoff);
            CP_ASYNC16(st + TILEB + sw,     Alo + aoff);
            CP_ASYNC16(st + 2 * TILEB + sw, Bf + boff);
        }
    };

    // Fragment load for slot idx in [0,8): pass p = idx>>2 (0: Ahi, 1: Alo),
    // kstep ks = idx&3.
    auto load_frags = [&](uint32_t st, int idx,
                          uint32_t (*af)[4], uint32_t (*bf_)[2]) {
        const int p = idx >> 2;
        const int ks = idx & 3;
        const uint32_t sa = st + (p ? TILEB : 0u);
        const uint32_t sb = st + 2 * TILEB;
        #pragma unroll
        for (int mt = 0; mt < 2; ++mt) {
            uint32_t ad = sa + SW128((uint32_t)((arow_base + mt * 16) * 128 +
                                                ks * 32 + akoff));
            LDSM_X4(af[mt][0], af[mt][1], af[mt][2], af[mt][3], ad);
        }
        #pragma unroll
        for (int bt = 0; bt < 2; ++bt) {
            uint32_t bd = sb + SW128((uint32_t)((brow_base + bt * 16) * 128 +
                                                ks * 32 + bkoff));
            LDSM_X4(bf_[2 * bt][0], bf_[2 * bt][1],
                    bf_[2 * bt + 1][0], bf_[2 * bt + 1][1], bd);
        }
    };

    load_stage(0, 0); CP_COMMIT();
    load_stage(1, 1); CP_COMMIT();

    uint32_t af[2][2][4];
    uint32_t bf_[2][4][2];

    for (int kt = 0; kt < NKT; ++kt) {
        CP_WAIT(STAGES - 2);
        __syncthreads();

        int nxt = kt + STAGES - 1;
        if (nxt < NKT) load_stage(nxt % STAGES, nxt);
        CP_COMMIT();

        const uint32_t st = sbase + (kt % STAGES) * STAGE_BYTES;

        load_frags(st, 0, af[0], bf_[0]);
        #pragma unroll
        for (int idx = 0; idx < 8; ++idx) {
            const int cur = idx & 1;
            if (idx < 7) load_frags(st, idx + 1, af[cur ^ 1], bf_[cur ^ 1]);
            #pragma unroll
            for (int mt = 0; mt < 2; ++mt)
                #pragma unroll
                for (int nt = 0; nt < 4; ++nt)
                    mma16816(acc[mt][nt], af[cur][mt], bf_[cur][nt]);
        }
    }

    // epilogue
    const int g = lid >> 2;
    const int t = lid & 3;
    #pragma unroll
    for (int mt = 0; mt < 2; ++mt) {
        #pragma unroll
        for (int nt = 0; nt < 4; ++nt) {
            int row0 = m0 + wm * 32 + mt * 16 + g;
            int col  = n0 + wn * 32 + nt * 8 + 2 * t;
            float bx = 0.f, by = 0.f;
            if (bias != nullptr) {
                float2 bv = *reinterpret_cast<const float2*>(bias + col);
                bx = bv.x; by = bv.y;
            }
            float2 v0 = make_float2(acc[mt][nt][0] + bx, acc[mt][nt][1] + by);
            float2 v1 = make_float2(acc[mt][nt][2] + bx, acc[mt][nt][3] + by);
            *reinterpret_cast<float2*>(C + (size_t)row0 * FDIM + col) = v0;
            *reinterpret_cast<float2*>(C + (size_t)(row0 + 8) * FDIM + col) = v1;
        }
    }
}

// ============================================================================
// Per-token attention core (fp32), float4-vectorized smem traffic.
// Outputs fp16 hi/lo for the final GEMM.
// ============================================================================
__global__ void __launch_bounds__(128) middle_kernel(
    const float* __restrict__ q, const float* __restrict__ k,
    const float* __restrict__ v,
    __half* __restrict__ mhi, __half* __restrict__ mlo)
{
    __shared__ float sq[1024];
    __shared__ float sk[1024];
    __shared__ float sv[1024];
    __shared__ float sat[64 * 65];

    const int t = blockIdx.x;
    const int tid = threadIdx.x;
    const size_t base = (size_t)t * 1024;

    {
        const float4* qs = reinterpret_cast<const float4*>(q + base);
        const float4* ks = reinterpret_cast<const float4*>(k + base);
        const float4* vs = reinterpret_cast<const float4*>(v + base);
        float4* dq = reinterpret_cast<float4*>(sq);
        float4* dk = reinterpret_cast<float4*>(sk);
        float4* dv = reinterpret_cast<float4*>(sv);
        dq[tid] = qs[tid]; dq[tid + 128] = qs[tid + 128];
        dk[tid] = ks[tid]; dk[tid + 128] = ks[tid + 128];
        dv[tid] = vs[tid]; dv[tid + 128] = vs[tid + 128];
    }
    __syncthreads();

    const int d = tid & 63;
    const int cg = tid >> 6;

    float qreg[16];
    #pragma unroll
    for (int h = 0; h < 16; ++h) qreg[h] = sq[h * 64 + d];

    #pragma unroll
    for (int cb = 0; cb < 8; ++cb) {
        const int c0 = cg * 32 + cb * 4;
        float4 a4 = make_float4(0.f, 0.f, 0.f, 0.f);
        #pragma unroll
        for (int h = 0; h < 16; ++h) {
            float4 k4 = *reinterpret_cast<const float4*>(&sk[h * 64 + c0]);
            float qh = qreg[h];
            a4.x += k4.x * qh; a4.y += k4.y * qh;
            a4.z += k4.z * qh; a4.w += k4.w * qh;
        }
        sat[(c0 + 0) * 65 + d] = a4.x * 0.125f;
        sat[(c0 + 1) * 65 + d] = a4.y * 0.125f;
        sat[(c0 + 2) * 65 + d] = a4.z * 0.125f;
        sat[(c0 + 3) * 65 + d] = a4.w * 0.125f;
    }
    __syncthreads();

    if (tid < 64) {
        const int c = tid;
        float m = -1e30f;
        for (int dd = 0; dd < 64; ++dd) m = fmaxf(m, sat[c * 65 + dd]);
        float s = 0.f;
        for (int dd = 0; dd < 64; ++dd) {
            float e = __expf(sat[c * 65 + dd] - m);
            sat[c * 65 + dd] = e;
            s += e;
        }
        float inv = 1.f / s;
        for (int dd = 0; dd < 64; ++dd) sat[c * 65 + dd] *= inv;
    }
    __syncthreads();

    float a8[8];
    #pragma unroll
    for (int j = 0; j < 8; ++j) a8[j] = 0.f;
    #pragma unroll 4
    for (int vb = 0; vb < 16; ++vb) {
        const int v0 = vb * 4;
        float s0 = sat[(v0 + 0) * 65 + d];
        float s1 = sat[(v0 + 1) * 65 + d];
        float s2 = sat[(v0 + 2) * 65 + d];
        float s3 = sat[(v0 + 3) * 65 + d];
        #pragma unroll
        for (int j = 0; j < 8; ++j) {
            float4 v4 = *reinterpret_cast<const float4*>(&sv[(cg * 8 + j) * 64 + v0]);
            a8[j] += v4.x * s0 + v4.y * s1 + v4.z * s2 + v4.w * s3;
        }
    }
    #pragma unroll
    for (int j = 0; j < 8; ++j) {
        float x = a8[j];
        __half h = __float2half(x);
        __half l = __float2half(x - __half2float(h));
        size_t idx = base + (size_t)(cg * 8 + j) * 64 + d;
        mhi[idx] = h;
        mlo[idx] = l;
    }
}

// ============================================================================
// kernel_launch: [split_all, gemmQ, gemmK, gemmV, middle, gemmO]
// ============================================================================
extern "C" void kernel_launch(void* const* d_in, const int* in_sizes, int n_in,
                              void* d_out, int out_size)
{
    const float* x1 = (const float*)d_in[0];
    const float* x2 = (const float*)d_in[1];
    const float* Wq = (const float*)d_in[2];
    const float* Wk = (const float*)d_in[3];
    const float* Wv = (const float*)d_in[4];
    const float* Wo = (const float*)d_in[5];
    const float* bo = (const float*)d_in[6];
    float* out = (float*)d_out;

    void *px1h, *px1l, *px2h, *px2l;
    void *pwq, *pwk, *pwv, *pwo;
    void *pq1, *pk2, *pv2, *pmh, *pml;
    cudaGetSymbolAddress(&px1h, g_x1hi); cudaGetSymbolAddress(&px1l, g_x1lo);
    cudaGetSymbolAddress(&px2h, g_x2hi); cudaGetSymbolAddress(&px2l, g_x2lo);
    cudaGetSymbolAddress(&pwq, g_wqf);   cudaGetSymbolAddress(&pwk, g_wkf);
    cudaGetSymbolAddress(&pwv, g_wvf);   cudaGetSymbolAddress(&pwo, g_wof);
    cudaGetSymbolAddress(&pq1, g_q1);    cudaGetSymbolAddress(&pk2, g_k2);
    cudaGetSymbolAddress(&pv2, g_v2);
    cudaGetSymbolAddress(&pmh, g_mhi);   cudaGetSymbolAddress(&pml, g_mlo);

    cudaFuncSetAttribute(gemm_hmma_kernel,
                         cudaFuncAttributeMaxDynamicSharedMemorySize, GEMM_SMEM);

    const int n4x = NELEM_X / 4;   // 4,194,304
    const int n4w = NELEM_W / 4;   // 262,144

    SplitArgs sa;
    sa.in[0] = x1; sa.hi[0] = (__half*)px1h; sa.lo[0] = (__half*)px1l; sa.n4[0] = n4x;
    sa.in[1] = x2; sa.hi[1] = (__half*)px2h; sa.lo[1] = (__half*)px2l; sa.n4[1] = n4x;
    sa.in[2] = Wq; sa.hi[2] = (__half*)pwq;  sa.lo[2] = nullptr;       sa.n4[2] = n4w;
    sa.in[3] = Wk; sa.hi[3] = (__half*)pwk;  sa.lo[3] = nullptr;       sa.n4[3] = n4w;
    sa.in[4] = Wv; sa.hi[4] = (__half*)pwv;  sa.lo[4] = nullptr;       sa.n4[4] = n4w;
    sa.in[5] = Wo; sa.hi[5] = (__half*)pwo;  sa.lo[5] = nullptr;       sa.n4[5] = n4w;

    dim3 sg(n4x / 256, 6);
    split_all_kernel<<<sg, 256>>>(sa);

    dim3 gg(FDIM / BN, NTOK / BM);   // (8, 128)
    gemm_hmma_kernel<<<gg, 512, GEMM_SMEM>>>(
        (const __half*)px1h, (const __half*)px1l, (const __half*)pwq,
        (float*)pq1, nullptr);
    gemm_hmma_kernel<<<gg, 512, GEMM_SMEM>>>(
        (const __half*)px2h, (const __half*)px2l, (const __half*)pwk,
        (float*)pk2, nullptr);
    gemm_hmma_kernel<<<gg, 512, GEMM_SMEM>>>(
        (const __half*)px2h, (const __half*)px2l, (const __half*)pwv,
        (float*)pv2, nullptr);

    middle_kernel<<<NTOK, 128>>>(
        (const float*)pq1, (const float*)pk2, (const float*)pv2,
        (__half*)pmh, (__half*)pml);

    gemm_hmma_kernel<<<gg, 512, GEMM_SMEM>>>(
        (const __half*)pmh, (const __half*)pml, (const __half*)pwo,
        out, bo);
}